// round 2
// baseline (speedup 1.0000x reference)
#include <cuda_runtime.h>
#include <math.h>

// ---------------- problem constants ----------------
#define B    8
#define C    128
#define Fk   8        // f dim (k=0 is c0, 1..7 are c_rest)
#define K    7
#define H64  64
#define HW   4096
#define HP   256
#define HWQ  4        // hw quarters (1024 px each)
#define CG   16       // channel groups
#define CPG  8        // channels per group
#define NCHUNK (B * HWQ * CG)   // 512
#define TPB  256

#define OUT1_ELEMS ((size_t)B * 257 * HW)
#define OUT2_ELEMS ((size_t)B * HW)

// ---------------- scratch ----------------
__device__ float g_t[B * HW];
__device__ float g_m[B * K * HW];
__device__ float g_partG[NCHUNK * K];
__device__ float g_partS[B * HWQ * K];
__device__ unsigned g_cnt = 0;
__device__ unsigned g_gen = 0;

// ---------------- grid barrier (persistent-kernel, graph-replay safe) -------
__device__ __forceinline__ void grid_barrier() {
    __syncthreads();
    if (threadIdx.x == 0) {
        __threadfence();
        unsigned my_gen = atomicAdd(&g_gen, 0u);
        unsigned old = atomicAdd(&g_cnt, 1u);
        if (old == gridDim.x - 1) {
            g_cnt = 0;              // only last arriver touches; others spin on gen
            __threadfence();
            atomicAdd(&g_gen, 1u);
        } else {
            while (atomicAdd(&g_gen, 0u) == my_gen) __nanosleep(64);
        }
        __threadfence();
    }
    __syncthreads();
}

// resize 256->64 linear(antialias=False) + threshold: avg of 2x2 at (4i+1,4j+1)
__device__ __forceinline__ float mask_at(const float* __restrict__ p, int i, int j) {
    int r0 = 4 * i + 1, q0 = 4 * j + 1;
    float a = p[r0 * HP + q0];
    float b = p[r0 * HP + q0 + 1];
    float c = p[(r0 + 1) * HP + q0];
    float d = p[(r0 + 1) * HP + q0 + 1];
    float y = 0.25f * (a + b + c + d);
    return (y > 0.5f) ? 1.0f : 0.0f;
}

// ============================================================
// single persistent kernel: masks -> barrier -> pass1 -> barrier -> pass2
// ============================================================
__global__ __launch_bounds__(TPB)
void k_fused(const float* __restrict__ feats,
             const float* __restrict__ vt,
             const float* __restrict__ va,
             float* __restrict__ out,
             int write_second) {
    extern __shared__ float4 sbuf[];        // K*TPB float4 = 28 KB (phase2 e-weights)
    __shared__ float red[8][14];
    __shared__ float sgs[K];
    const int tid  = threadIdx.x;
    const int lane = tid & 31;
    const int wrp  = tid >> 5;
    const unsigned NB = gridDim.x;

    // ---------------- phase 0: masks ----------------
    for (int idx = blockIdx.x * TPB + tid; idx < B * HW; idx += NB * TPB) {
        int b  = idx >> 12;
        int hw = idx & (HW - 1);
        int i  = hw >> 6;
        int j  = hw & 63;
        g_t[idx] = mask_at(vt + (size_t)b * HP * HP, i, j);
        #pragma unroll
        for (int k = 0; k < K; k++)
            g_m[((size_t)b * K + k) * HW + hw] =
                mask_at(va + ((size_t)b * K + k) * HP * HP, i, j);
    }

    grid_barrier();

    // ---------------- phase 1: partial G, S ----------------
    for (int chunk = blockIdx.x; chunk < NCHUNK; chunk += NB) {
        int cg  = chunk & (CG - 1);
        int hwq = (chunk >> 4) & (HWQ - 1);
        int b   = chunk >> 6;
        int hw0 = hwq * 1024 + tid * 4;

        const float4 t4 = *(const float4*)(g_t + b * HW + hw0);
        const float* base = feats + ((size_t)(b * C + cg * CPG)) * Fk * HW + hw0;

        float vals[2 * K];
        #pragma unroll
        for (int k = 0; k < K; k++) {
            float4 m4 = *(const float4*)(g_m + ((size_t)(b * K + k)) * HW + hw0);
            float4 w;
            w.x = t4.x * m4.x; w.y = t4.y * m4.y;
            w.z = t4.z * m4.z; w.w = t4.w * m4.w;

            float4 a = make_float4(0.f, 0.f, 0.f, 0.f);
            #pragma unroll
            for (int c = 0; c < CPG; c++) {
                const float* p = base + (size_t)c * Fk * HW;
                float4 c0 = *(const float4*)p;                       // L1-hot after k=0
                float4 r  = *(const float4*)(p + (size_t)(k + 1) * HW);
                a.x = fmaf(c0.x, r.x, a.x);
                a.y = fmaf(c0.y, r.y, a.y);
                a.z = fmaf(c0.z, r.z, a.z);
                a.w = fmaf(c0.w, r.w, a.w);
            }
            // sum_c w*c0*cr = w . (sum_c c0*cr)
            vals[k]     = w.x * a.x + w.y * a.y + w.z * a.z + w.w * a.w;
            vals[K + k] = w.x + w.y + w.z + w.w;
        }

        // block-reduce 14 scalars (deterministic)
        #pragma unroll
        for (int v = 0; v < 2 * K; v++) {
            float x = vals[v];
            #pragma unroll
            for (int o = 16; o > 0; o >>= 1) x += __shfl_down_sync(0xFFFFFFFFu, x, o);
            if (lane == 0) red[wrp][v] = x;
        }
        __syncthreads();
        if (tid < 2 * K) {
            float x = 0.f;
            #pragma unroll
            for (int w = 0; w < 8; w++) x += red[w][tid];
            if (tid < K)
                g_partG[chunk * K + tid] = x;
            else if (cg == 0)
                g_partS[(b * HWQ + hwq) * K + (tid - K)] = x;
        }
        __syncthreads();
    }

    grid_barrier();

    // ---------------- phase 2: softmax + weighted sum ----------------
    for (int chunk = blockIdx.x; chunk < NCHUNK; chunk += NB) {
        int cg  = chunk & (CG - 1);
        int hwq = (chunk >> 4) & (HWQ - 1);
        int b   = chunk >> 6;
        int hw0 = hwq * 1024 + tid * 4;

        // gs for this b (fixed-order, deterministic; tiny)
        __syncthreads();
        if (tid < K) {
            float G = 0.f;
            #pragma unroll 8
            for (int j = 0; j < HWQ * CG; j++) G += g_partG[(b * HWQ * CG + j) * K + tid];
            float S = 0.f;
            #pragma unroll
            for (int j = 0; j < HWQ; j++) S += g_partS[(b * HWQ + j) * K + tid];
            sgs[tid] = (S < 1e-4f) ? 0.f : G / (S * (float)C);
        }
        __syncthreads();

        // per-pixel masked softmax over k (mask = v_r only)
        const float* mb = g_m + (size_t)b * K * HW + hw0;
        float4 mx;
        {
            float4 m4 = *(const float4*)mb;
            mx.x = sgs[0] * m4.x; mx.y = sgs[0] * m4.y;
            mx.z = sgs[0] * m4.z; mx.w = sgs[0] * m4.w;
        }
        #pragma unroll
        for (int k = 1; k < K; k++) {
            float4 m4 = *(const float4*)(mb + (size_t)k * HW);
            mx.x = fmaxf(mx.x, sgs[k] * m4.x);
            mx.y = fmaxf(mx.y, sgs[k] * m4.y);
            mx.z = fmaxf(mx.z, sgs[k] * m4.z);
            mx.w = fmaxf(mx.w, sgs[k] * m4.w);
        }
        float4 s = make_float4(0.f, 0.f, 0.f, 0.f);
        #pragma unroll
        for (int k = 0; k < K; k++) {
            float4 m4 = *(const float4*)(mb + (size_t)k * HW);
            float4 e;
            e.x = __expf(sgs[k] * m4.x - mx.x) * m4.x;
            e.y = __expf(sgs[k] * m4.y - mx.y) * m4.y;
            e.z = __expf(sgs[k] * m4.z - mx.z) * m4.z;
            e.w = __expf(sgs[k] * m4.w - mx.w) * m4.w;
            sbuf[k * TPB + tid] = e;
            s.x += e.x; s.y += e.y; s.z += e.z; s.w += e.w;
        }
        float4 inv;
        inv.x = 1.f / (s.x + ((s.x < 1e-4f) ? 1.f : 0.f));
        inv.y = 1.f / (s.y + ((s.y < 1e-4f) ? 1.f : 0.f));
        inv.z = 1.f / (s.z + ((s.z < 1e-4f) ? 1.f : 0.f));
        inv.w = 1.f / (s.w + ((s.w < 1e-4f) ? 1.f : 0.f));
        float4 cmask;                         // 1 - sum_k cm*m = 1 - s/s'
        cmask.x = 1.f - s.x * inv.x;
        cmask.y = 1.f - s.y * inv.y;
        cmask.z = 1.f - s.z * inv.z;
        cmask.w = 1.f - s.w * inv.w;

        const float* base = feats + ((size_t)(b * C + cg * CPG)) * Fk * HW + hw0;
        float* ob = out + (size_t)b * 257 * HW + hw0;

        #pragma unroll
        for (int c = 0; c < CPG; c++) {
            const float* p = base + (size_t)c * Fk * HW;
            float4 c0 = *(const float4*)p;
            float4 a = make_float4(0.f, 0.f, 0.f, 0.f);
            #pragma unroll
            for (int k = 0; k < K; k++) {
                float4 e = sbuf[k * TPB + tid];
                float4 r = *(const float4*)(p + (size_t)(k + 1) * HW);
                a.x = fmaf(e.x, r.x, a.x);
                a.y = fmaf(e.y, r.y, a.y);
                a.z = fmaf(e.z, r.z, a.z);
                a.w = fmaf(e.w, r.w, a.w);
            }
            a.x *= inv.x; a.y *= inv.y; a.z *= inv.z; a.w *= inv.w;
            int ch = cg * CPG + c;
            *(float4*)(ob + (size_t)ch * HW)         = c0;   // channels [0,128)
            *(float4*)(ob + (size_t)(128 + ch) * HW) = a;    // channels [128,256)
        }
        if (cg == 0) {
            *(float4*)(ob + (size_t)256 * HW) = cmask;       // channel 256
            if (write_second)
                *(float4*)(out + OUT1_ELEMS + (size_t)b * HW + hw0) = cmask;
        }
    }
}

// ============================================================
extern "C" void kernel_launch(void* const* d_in, const int* in_sizes, int n_in,
                              void* d_out, int out_size) {
    const float* feats = (const float*)d_in[0];   // (8,128,8,64,64)
    const float* vt    = (const float*)d_in[1];   // (8,1,256,256)
    const float* va    = (const float*)d_in[2];   // (8,1,7,256,256)
    float* out = (float*)d_out;

    int write_second = ((size_t)out_size >= OUT1_ELEMS + OUT2_ELEMS) ? 1 : 0;

    const int smem = K * TPB * sizeof(float4);    // 28 KB

    int dev = 0;
    cudaGetDevice(&dev);
    int sms = 0;
    cudaDeviceGetAttribute(&sms, cudaDevAttrMultiProcessorCount, dev);
    int occ = 0;
    cudaOccupancyMaxActiveBlocksPerMultiprocessor(&occ, k_fused, TPB, smem);
    int grid = sms * occ;                          // guaranteed co-resident capacity
    if (grid > NCHUNK) grid = NCHUNK;
    if (grid < 1) grid = 1;

    k_fused<<<grid, TPB, smem>>>(feats, vt, va, out, write_second);
}

// round 3
// speedup vs baseline: 1.2393x; 1.2393x over previous
#include <cuda_runtime.h>
#include <math.h>

// ---------------- problem constants ----------------
#define B    8
#define C    128
#define Fk   8        // f dim (index 0 is c0, 1..7 are c_rest)
#define K    7
#define H64  64
#define HW   4096
#define HP   256
#define HWQ  4        // hw quarters: 1024 px each, 256 threads x float4
#define NCC  32       // channel groups
#define CPG  4        // channels per group
#define NCHUNK (B * HWQ * NCC)   // 1024 blocks for the two big passes
#define TPB  256

#define OUT1_ELEMS ((size_t)B * 257 * HW)
#define OUT2_ELEMS ((size_t)B * HW)

// ---------------- scratch ----------------
__device__ float g_t[B * HW];
__device__ float g_m[B * K * HW];
__device__ float g_partG[NCHUNK * K];
__device__ float g_partS[B * HWQ * K];
__device__ float g_gs[B * K];

// ============================================================
// Kernel 1: resize masks 256->64 (linear, antialias=False) + threshold.
// out[i,j] = avg of in[{4i+1,4i+2} x {4j+1,4j+2}] > 0.5
// Columns {4j+1,4j+2} live inside the aligned float4 at column 4j ->
// 2 x LDG.128 per mask value.
// ============================================================
__device__ __forceinline__ float mask_at4(const float* __restrict__ p, int r0, int j) {
    float4 a = *(const float4*)(p + (size_t)r0 * HP + 4 * j);
    float4 b = *(const float4*)(p + (size_t)(r0 + 1) * HP + 4 * j);
    float y = 0.25f * (a.y + a.z + b.y + b.z);
    return (y > 0.5f) ? 1.0f : 0.0f;
}

__global__ __launch_bounds__(TPB)
void k_masks(const float* __restrict__ vt, const float* __restrict__ va) {
    int idx = blockIdx.x * TPB + threadIdx.x;   // 0 .. B*HW-1
    int b  = idx >> 12;
    int hw = idx & (HW - 1);
    int i  = hw >> 6;
    int j  = hw & 63;
    int r0 = 4 * i + 1;

    g_t[idx] = mask_at4(vt + (size_t)b * HP * HP, r0, j);
    #pragma unroll
    for (int k = 0; k < K; k++)
        g_m[((size_t)b * K + k) * HW + hw] =
            mask_at4(va + ((size_t)b * K + k) * HP * HP, r0, j);
}

// ============================================================
// Kernel 2: partial reductions for S[b,k], G[b,k].
// grid = 1024: (b, hwq, cg). 256 threads x float4 = 1024 px, 4 channels.
// ============================================================
__global__ __launch_bounds__(TPB)
void k_pass1(const float* __restrict__ feats) {
    __shared__ float red[8][2 * K];
    const int tid  = threadIdx.x;
    const int lane = tid & 31;
    const int wrp  = tid >> 5;

    int chunk = blockIdx.x;
    int cg  = chunk & (NCC - 1);
    int hwq = (chunk >> 5) & (HWQ - 1);
    int b   = chunk >> 7;
    int hw0 = hwq * 1024 + tid * 4;

    const float4 t4 = *(const float4*)(g_t + b * HW + hw0);
    const float* base = feats + ((size_t)(b * C + cg * CPG)) * Fk * HW + hw0;

    float vals[2 * K];
    #pragma unroll
    for (int k = 0; k < K; k++) {
        float4 m4 = *(const float4*)(g_m + ((size_t)(b * K + k)) * HW + hw0);
        float4 w;
        w.x = t4.x * m4.x; w.y = t4.y * m4.y;
        w.z = t4.z * m4.z; w.w = t4.w * m4.w;

        float4 a = make_float4(0.f, 0.f, 0.f, 0.f);
        #pragma unroll
        for (int c = 0; c < CPG; c++) {
            const float* p = base + (size_t)c * Fk * HW;
            float4 c0 = *(const float4*)p;                        // L1-hot for k>0
            float4 r  = *(const float4*)(p + (size_t)(k + 1) * HW);
            a.x = fmaf(c0.x, r.x, a.x);
            a.y = fmaf(c0.y, r.y, a.y);
            a.z = fmaf(c0.z, r.z, a.z);
            a.w = fmaf(c0.w, r.w, a.w);
        }
        // sum_c w*c0*cr = w . (sum_c c0*cr)
        vals[k]     = w.x * a.x + w.y * a.y + w.z * a.z + w.w * a.w;
        vals[K + k] = w.x + w.y + w.z + w.w;
    }

    #pragma unroll
    for (int v = 0; v < 2 * K; v++) {
        float x = vals[v];
        #pragma unroll
        for (int o = 16; o > 0; o >>= 1) x += __shfl_down_sync(0xFFFFFFFFu, x, o);
        if (lane == 0) red[wrp][v] = x;
    }
    __syncthreads();
    if (tid < 2 * K) {
        float x = 0.f;
        #pragma unroll
        for (int w = 0; w < 8; w++) x += red[w][tid];
        if (tid < K)
            g_partG[chunk * K + tid] = x;
        else if (cg == 0)
            g_partS[(b * HWQ + hwq) * K + (tid - K)] = x;
    }
}

// ============================================================
// Kernel 3: final gs[b,k] (fixed-order, deterministic)
// ============================================================
__global__ void k_gs() {
    int i = threadIdx.x;          // b*K index
    if (i >= B * K) return;
    int b = i / K, k = i % K;
    float G = 0.f;
    #pragma unroll 8
    for (int j = 0; j < HWQ * NCC; j++)
        G += g_partG[(size_t)(b * HWQ * NCC + j) * K + k];
    float S = 0.f;
    #pragma unroll
    for (int j = 0; j < HWQ; j++)
        S += g_partS[(size_t)(b * HWQ + j) * K + k];
    g_gs[i] = (S < 1e-4f) ? 0.f : G / (S * (float)C);
}

// ============================================================
// Kernel 4: per-pixel masked softmax over k + weighted channel sum.
// grid = 1024 (reversed traversal), smem holds cm weights (28 KB).
// ============================================================
__global__ __launch_bounds__(TPB)
void k_pass2(const float* __restrict__ feats, float* __restrict__ out,
             int write_second) {
    __shared__ float4 cmbuf[K * TPB];      // 28 KB
    __shared__ float sgs[K];
    const int tid = threadIdx.x;

    int bid = (gridDim.x - 1) - blockIdx.x;   // reversed vs pass1
    int cg  = bid & (NCC - 1);
    int hwq = (bid >> 5) & (HWQ - 1);
    int b   = bid >> 7;
    int hw0 = hwq * 1024 + tid * 4;

    if (tid < K) sgs[tid] = g_gs[b * K + tid];
    __syncthreads();

    const float* mb = g_m + (size_t)b * K * HW + hw0;

    float4 mx;
    {
        float4 m4 = *(const float4*)mb;
        mx.x = sgs[0] * m4.x; mx.y = sgs[0] * m4.y;
        mx.z = sgs[0] * m4.z; mx.w = sgs[0] * m4.w;
    }
    #pragma unroll
    for (int k = 1; k < K; k++) {
        float4 m4 = *(const float4*)(mb + (size_t)k * HW);
        mx.x = fmaxf(mx.x, sgs[k] * m4.x);
        mx.y = fmaxf(mx.y, sgs[k] * m4.y);
        mx.z = fmaxf(mx.z, sgs[k] * m4.z);
        mx.w = fmaxf(mx.w, sgs[k] * m4.w);
    }
    float4 s = make_float4(0.f, 0.f, 0.f, 0.f);
    float4 e[K];
    #pragma unroll
    for (int k = 0; k < K; k++) {
        float4 m4 = *(const float4*)(mb + (size_t)k * HW);
        e[k].x = __expf(sgs[k] * m4.x - mx.x) * m4.x;
        e[k].y = __expf(sgs[k] * m4.y - mx.y) * m4.y;
        e[k].z = __expf(sgs[k] * m4.z - mx.z) * m4.z;
        e[k].w = __expf(sgs[k] * m4.w - mx.w) * m4.w;
        s.x += e[k].x; s.y += e[k].y; s.z += e[k].z; s.w += e[k].w;
    }
    float4 inv;
    inv.x = 1.f / (s.x + ((s.x < 1e-4f) ? 1.f : 0.f));
    inv.y = 1.f / (s.y + ((s.y < 1e-4f) ? 1.f : 0.f));
    inv.z = 1.f / (s.z + ((s.z < 1e-4f) ? 1.f : 0.f));
    inv.w = 1.f / (s.w + ((s.w < 1e-4f) ? 1.f : 0.f));
    #pragma unroll
    for (int k = 0; k < K; k++) {
        float4 cm;
        cm.x = e[k].x * inv.x; cm.y = e[k].y * inv.y;
        cm.z = e[k].z * inv.z; cm.w = e[k].w * inv.w;
        cmbuf[k * TPB + tid] = cm;
    }
    __syncthreads();

    const float* base = feats + ((size_t)(b * C + cg * CPG)) * Fk * HW + hw0;
    float* ob = out + (size_t)b * 257 * HW + hw0;

    #pragma unroll
    for (int c = 0; c < CPG; c++) {
        const float* p = base + (size_t)c * Fk * HW;
        float4 c0 = *(const float4*)p;
        float4 a = make_float4(0.f, 0.f, 0.f, 0.f);
        #pragma unroll
        for (int k = 0; k < K; k++) {
            float4 cm = cmbuf[k * TPB + tid];
            float4 r  = *(const float4*)(p + (size_t)(k + 1) * HW);
            a.x = fmaf(cm.x, r.x, a.x);
            a.y = fmaf(cm.y, r.y, a.y);
            a.z = fmaf(cm.z, r.z, a.z);
            a.w = fmaf(cm.w, r.w, a.w);
        }
        int ch = cg * CPG + c;
        *(float4*)(ob + (size_t)ch * HW)         = c0;   // channels [0,128): c0
        *(float4*)(ob + (size_t)(128 + ch) * HW) = a;    // channels [128,256)
    }
    if (cg == 0) {
        float4 cmask;                      // 1 - sum_k cm*m = 1 - s*inv
        cmask.x = 1.f - s.x * inv.x;
        cmask.y = 1.f - s.y * inv.y;
        cmask.z = 1.f - s.z * inv.z;
        cmask.w = 1.f - s.w * inv.w;
        *(float4*)(ob + (size_t)256 * HW) = cmask;       // channel 256
        if (write_second)
            *(float4*)(out + OUT1_ELEMS + (size_t)b * HW + hw0) = cmask;
    }
}

// ============================================================
extern "C" void kernel_launch(void* const* d_in, const int* in_sizes, int n_in,
                              void* d_out, int out_size) {
    const float* feats = (const float*)d_in[0];   // (8,128,8,64,64)
    const float* vt    = (const float*)d_in[1];   // (8,1,256,256)
    const float* va    = (const float*)d_in[2];   // (8,1,7,256,256)
    float* out = (float*)d_out;

    int write_second = ((size_t)out_size >= OUT1_ELEMS + OUT2_ELEMS) ? 1 : 0;

    k_masks<<<(B * HW) / TPB, TPB>>>(vt, va);
    k_pass1<<<NCHUNK, TPB>>>(feats);
    k_gs<<<1, 64>>>();
    k_pass2<<<NCHUNK, TPB>>>(feats, out, write_second);
}

// round 7
// speedup vs baseline: 1.3197x; 1.0649x over previous
#include <cuda_runtime.h>
#include <math.h>

// ---------------- problem constants ----------------
#define B    8
#define C    128
#define Fk   8        // f dim (index 0 is c0, 1..7 are c_rest)
#define K    7
#define H64  64
#define HW   4096
#define HP   256
#define HWQ  4        // hw quarters: 1024 px each, 256 threads x float4
#define NCC  32       // channel groups
#define CPG  4        // channels per group
#define NCHUNK (B * HWQ * NCC)   // 1024 blocks for the two big passes
#define TPB  256

#define OUT1_ELEMS ((size_t)B * 257 * HW)
#define OUT2_ELEMS ((size_t)B * HW)

// ---------------- scratch ----------------
__device__ float g_t[B * HW];
__device__ float g_m[B * K * HW];
__device__ float g_cm[B * K * HW];           // softmax weights (917 KB, L2-hot)
__device__ float g_partG[NCHUNK * K];
__device__ float g_partS[B * HWQ * K];

// ============================================================
// Kernel 1: resize masks 256->64 (linear, antialias=False) + threshold.
// out[i,j] = avg of in[{4i+1,4i+2} x {4j+1,4j+2}] > 0.5
// ============================================================
__device__ __forceinline__ float mask_at4(const float* __restrict__ p, int r0, int j) {
    float4 a = *(const float4*)(p + (size_t)r0 * HP + 4 * j);
    float4 b = *(const float4*)(p + (size_t)(r0 + 1) * HP + 4 * j);
    float y = 0.25f * (a.y + a.z + b.y + b.z);
    return (y > 0.5f) ? 1.0f : 0.0f;
}

__global__ __launch_bounds__(TPB)
void k_masks(const float* __restrict__ vt, const float* __restrict__ va) {
    int idx = blockIdx.x * TPB + threadIdx.x;   // 0 .. B*HW-1
    int b  = idx >> 12;
    int hw = idx & (HW - 1);
    int i  = hw >> 6;
    int j  = hw & 63;
    int r0 = 4 * i + 1;

    g_t[idx] = mask_at4(vt + (size_t)b * HP * HP, r0, j);
    #pragma unroll
    for (int k = 0; k < K; k++)
        g_m[((size_t)b * K + k) * HW + hw] =
            mask_at4(va + ((size_t)b * K + k) * HP * HP, r0, j);
}

// ============================================================
// Kernel 2: partial reductions for S[b,k], G[b,k].
// grid = 1024: (b, hwq, cg). 256 threads x float4 = 1024 px, 4 channels.
// ============================================================
__global__ __launch_bounds__(TPB)
void k_pass1(const float* __restrict__ feats) {
    __shared__ float red[8][2 * K];
    const int tid  = threadIdx.x;
    const int lane = tid & 31;
    const int wrp  = tid >> 5;

    int chunk = blockIdx.x;
    int cg  = chunk & (NCC - 1);
    int hwq = (chunk >> 5) & (HWQ - 1);
    int b   = chunk >> 7;
    int hw0 = hwq * 1024 + tid * 4;

    const float4 t4 = *(const float4*)(g_t + b * HW + hw0);
    const float* base = feats + ((size_t)(b * C + cg * CPG)) * Fk * HW + hw0;

    float vals[2 * K];
    #pragma unroll
    for (int k = 0; k < K; k++) {
        float4 m4 = *(const float4*)(g_m + ((size_t)(b * K + k)) * HW + hw0);
        float4 w;
        w.x = t4.x * m4.x; w.y = t4.y * m4.y;
        w.z = t4.z * m4.z; w.w = t4.w * m4.w;

        float4 a = make_float4(0.f, 0.f, 0.f, 0.f);
        #pragma unroll
        for (int c = 0; c < CPG; c++) {
            const float* p = base + (size_t)c * Fk * HW;
            float4 c0 = *(const float4*)p;                        // L1-hot for k>0
            float4 r  = *(const float4*)(p + (size_t)(k + 1) * HW);
            a.x = fmaf(c0.x, r.x, a.x);
            a.y = fmaf(c0.y, r.y, a.y);
            a.z = fmaf(c0.z, r.z, a.z);
            a.w = fmaf(c0.w, r.w, a.w);
        }
        vals[k]     = w.x * a.x + w.y * a.y + w.z * a.z + w.w * a.w;
        vals[K + k] = w.x + w.y + w.z + w.w;
    }

    #pragma unroll
    for (int v = 0; v < 2 * K; v++) {
        float x = vals[v];
        #pragma unroll
        for (int o = 16; o > 0; o >>= 1) x += __shfl_down_sync(0xFFFFFFFFu, x, o);
        if (lane == 0) red[wrp][v] = x;
    }
    __syncthreads();
    if (tid < 2 * K) {
        float x = 0.f;
        #pragma unroll
        for (int w = 0; w < 8; w++) x += red[w][tid];
        if (tid < K)
            g_partG[chunk * K + tid] = x;
        else if (cg == 0)
            g_partS[(b * HWQ + hwq) * K + (tid - K)] = x;
    }
}

// ============================================================
// Kernel 3: per-pixel softmax weights cm[k] -> g_cm, plus c_mask outputs.
// grid = 128 blocks x 256 threads, one pixel per thread. Each block
// redundantly computes gs[b,*] from partials (L2-hot, deterministic order).
// ============================================================
__global__ __launch_bounds__(TPB)
void k_cm(float* __restrict__ out, int write_second) {
    __shared__ float sgs[K];
    const int tid = threadIdx.x;
    int idx = blockIdx.x * TPB + tid;
    int b   = idx >> 12;
    int hw  = idx & (HW - 1);

    if (tid < K) {
        float G = 0.f;
        #pragma unroll 8
        for (int j = 0; j < HWQ * NCC; j++)
            G += g_partG[(size_t)(b * HWQ * NCC + j) * K + tid];
        float S = 0.f;
        #pragma unroll
        for (int j = 0; j < HWQ; j++)
            S += g_partS[(size_t)(b * HWQ + j) * K + tid];
        sgs[tid] = (S < 1e-4f) ? 0.f : G / (S * (float)C);
    }
    __syncthreads();

    const float* mb = g_m + (size_t)b * K * HW + hw;
    float m[K];
    #pragma unroll
    for (int k = 0; k < K; k++) m[k] = mb[(size_t)k * HW];

    float mx = sgs[0] * m[0];
    #pragma unroll
    for (int k = 1; k < K; k++) mx = fmaxf(mx, sgs[k] * m[k]);

    float e[K], s = 0.f;
    #pragma unroll
    for (int k = 0; k < K; k++) {
        e[k] = __expf(sgs[k] * m[k] - mx) * m[k];
        s += e[k];
    }
    float inv = 1.f / (s + ((s < 1e-4f) ? 1.f : 0.f));

    float* cmb = g_cm + (size_t)b * K * HW + hw;
    #pragma unroll
    for (int k = 0; k < K; k++) cmb[(size_t)k * HW] = e[k] * inv;

    float cmask = 1.f - s * inv;     // 1 - sum_k cm*m
    out[(size_t)b * 257 * HW + (size_t)256 * HW + hw] = cmask;
    if (write_second)
        out[OUT1_ELEMS + (size_t)b * HW + hw] = cmask;
}

// ============================================================
// Kernel 4 (slim): weighted channel sum. Pure stream, low regs.
// The softmax lives in k_cm; this kernel only does LDS + LDG + FFMA + STG.
// ============================================================
__global__ __launch_bounds__(TPB)
void k_pass2(const float* __restrict__ feats, float* __restrict__ out) {
    __shared__ float4 cmbuf[K * TPB];      // 28 KB
    const int tid = threadIdx.x;

    int bid = (gridDim.x - 1) - blockIdx.x;   // reversed vs pass1
    int cg  = bid & (NCC - 1);
    int hwq = (bid >> 5) & (HWQ - 1);
    int b   = bid >> 7;
    int hw0 = hwq * 1024 + tid * 4;

    const float* cmg = g_cm + (size_t)b * K * HW + hw0;   // L2-hot
    #pragma unroll
    for (int k = 0; k < K; k++)
        cmbuf[k * TPB + tid] = *(const float4*)(cmg + (size_t)k * HW);
    __syncthreads();

    const float* base = feats + ((size_t)(b * C + cg * CPG)) * Fk * HW + hw0;
    float* ob = out + (size_t)b * 257 * HW + hw0;

    #pragma unroll
    for (int c = 0; c < CPG; c++) {
        const float* p = base + (size_t)c * Fk * HW;
        float4 c0 = *(const float4*)p;
        float4 a = make_float4(0.f, 0.f, 0.f, 0.f);
        #pragma unroll
        for (int k = 0; k < K; k++) {
            float4 cm = cmbuf[k * TPB + tid];
            float4 r  = *(const float4*)(p + (size_t)(k + 1) * HW);
            a.x = fmaf(cm.x, r.x, a.x);
            a.y = fmaf(cm.y, r.y, a.y);
            a.z = fmaf(cm.z, r.z, a.z);
            a.w = fmaf(cm.w, r.w, a.w);
        }
        int ch = cg * CPG + c;
        *(float4*)(ob + (size_t)ch * HW)         = c0;   // channels [0,128)
        *(float4*)(ob + (size_t)(128 + ch) * HW) = a;    // channels [128,256)
    }
}

// ============================================================
extern "C" void kernel_launch(void* const* d_in, const int* in_sizes, int n_in,
                              void* d_out, int out_size) {
    const float* feats = (const float*)d_in[0];   // (8,128,8,64,64)
    const float* vt    = (const float*)d_in[1];   // (8,1,256,256)
    const float* va    = (const float*)d_in[2];   // (8,1,7,256,256)
    float* out = (float*)d_out;

    int write_second = ((size_t)out_size >= OUT1_ELEMS + OUT2_ELEMS) ? 1 : 0;

    k_masks<<<(B * HW) / TPB, TPB>>>(vt, va);
    k_pass1<<<NCHUNK, TPB>>>(feats);
    k_cm<<<(B * HW) / TPB, TPB>>>(out, write_second);
    k_pass2<<<NCHUNK, TPB>>>(feats, out);
}